// round 4
// baseline (speedup 1.0000x reference)
#include <cuda_runtime.h>
#include <cuda_bf16.h>

#define B_BATCH 128

// Scratch (static device globals — allocation-free per harness rules)
__device__ float g_z1[128 * 64 * 48 * 48];   // conv1 out, NCHW
__device__ float g_z2[128 * 128 * 16 * 16];  // conv2 out, NCHW
__device__ float g_z3[64 * 128 * 13 * 13];   // conv3 out, [C][N] row-major
__device__ float g_cnorm[512];

// ---------------------------------------------------------------------------
// Implicit-GEMM convolution.
//   C[M=OC, N=B*OH*OW] = W[OC, K] * im2col(X)[K, N],  K = IC*KH*KW
// Block tile 64x64, K-tile 16, 256 threads, 4x4 register micro-tile.
// LAYOUT 0: write NCHW ((b*OC+oc)*OH*OW + p) ; LAYOUT 1: write [oc][n].
// ---------------------------------------------------------------------------
template <int IC, int KH, int KW, int IH, int IW, int OH, int OW,
          int STRIDE, int PAD, int OC, bool RELU, int LAYOUT>
__global__ __launch_bounds__(256) void conv_gemm_kernel(
    const float* __restrict__ x, const float* __restrict__ w,
    const float* __restrict__ bias, float* __restrict__ out)
{
    constexpr int K    = IC * KH * KW;
    constexpr int OHW  = OH * OW;
    constexpr int NTOT = B_BATCH * OHW;

    __shared__ float As[16][66];   // pad 66: conflict-free transposed store, 8B-aligned rows
    __shared__ float Bs[16][64];

    const int tid = threadIdx.x;
    const int tx  = tid & 15;      // N direction
    const int ty  = tid >> 4;      // M direction

    const int m0 = blockIdx.y * 64;
    const int n0 = blockIdx.x * 64;

    // --- B-tile loader coords (fixed n per thread across K loop) ---
    const int bn  = tid & 63;
    const int bk  = tid >> 6;            // 0..3
    const int ng  = n0 + bn;
    const int nb  = ng / OHW;
    const int np  = ng % OHW;
    const int oh  = np / OW;
    const int ow  = np % OW;
    const int ih0 = oh * STRIDE - PAD;
    const int iw0 = ow * STRIDE - PAD;
    const float* xb = x + (size_t)nb * (IC * IH * IW);

    // --- A-tile loader coords ---
    const int am = tid >> 2;             // 0..63
    const int ak = (tid & 3) * 4;        // 0,4,8,12
    const float* wrow = w + (size_t)(m0 + am) * K;

    float acc[4][4];
#pragma unroll
    for (int i = 0; i < 4; i++)
#pragma unroll
        for (int j = 0; j < 4; j++) acc[i][j] = 0.f;

    for (int k0 = 0; k0 < K; k0 += 16) {
        // load A tile (transposed into smem)
        float4 av = *reinterpret_cast<const float4*>(wrow + k0 + ak);
        As[ak + 0][am] = av.x;
        As[ak + 1][am] = av.y;
        As[ak + 2][am] = av.z;
        As[ak + 3][am] = av.w;

        // load B tile via on-the-fly im2col gather
#pragma unroll
        for (int i = 0; i < 4; i++) {
            const int kl = bk + i * 4;
            const int kg = k0 + kl;
            const int ic = kg / (KH * KW);
            const int r  = kg % (KH * KW);
            const int kh = r / KW;
            const int kw = r % KW;
            const int ih = ih0 + kh;
            const int iw = iw0 + kw;
            float v = 0.f;
            if (ih >= 0 && ih < IH && iw >= 0 && iw < IW)
                v = xb[(ic * IH + ih) * IW + iw];
            Bs[kl][bn] = v;
        }
        __syncthreads();

#pragma unroll
        for (int k = 0; k < 16; k++) {
            float2 a01 = *reinterpret_cast<const float2*>(&As[k][ty * 4]);
            float2 a23 = *reinterpret_cast<const float2*>(&As[k][ty * 4 + 2]);
            float4 bv  = *reinterpret_cast<const float4*>(&Bs[k][tx * 4]);
            const float a[4] = {a01.x, a01.y, a23.x, a23.y};
            const float b[4] = {bv.x, bv.y, bv.z, bv.w};
#pragma unroll
            for (int i = 0; i < 4; i++)
#pragma unroll
                for (int j = 0; j < 4; j++)
                    acc[i][j] += a[i] * b[j];
        }
        __syncthreads();
    }

    // --- epilogue: bias (+ReLU), vectorized store ---
    const int nout  = n0 + tx * 4;           // 4 consecutive n, same batch (OHW % 64 == 0 for LAYOUT 0)
    const int b_out = nout / OHW;
    const int p_out = nout % OHW;
#pragma unroll
    for (int i = 0; i < 4; i++) {
        const int oc = m0 + ty * 4 + i;
        const float bval = bias[oc];
        float4 v;
        float* vp = reinterpret_cast<float*>(&v);
#pragma unroll
        for (int j = 0; j < 4; j++) {
            float t = acc[i][j] + bval;
            if (RELU) t = fmaxf(t, 0.f);
            vp[j] = t;
        }
        if (LAYOUT == 0) {
            *reinterpret_cast<float4*>(out + (size_t)(b_out * OC + oc) * OHW + p_out) = v;
        } else {
            *reinterpret_cast<float4*>(out + (size_t)oc * NTOT + nout) = v;
        }
    }
}

// ---------------------------------------------------------------------------
// Codebook squared norms
// ---------------------------------------------------------------------------
__global__ void cnorm_kernel(const float* __restrict__ cb)
{
    const int i = blockIdx.x * blockDim.x + threadIdx.x;
    if (i < 512) {
        float s = 0.f;
#pragma unroll
        for (int c = 0; c < 64; c++) {
            const float v = cb[i * 64 + c];
            s += v * v;
        }
        g_cnorm[i] = s;
    }
}

// ---------------------------------------------------------------------------
// VQ argmin + one-hot scatter.
// z3 layout [64][21632]  (coalesced per-warp loads).
// score = ||c||^2 - 2 z.c   (||z||^2 is row-constant — argmin-invariant).
// Strict < keeps the first minimum (matches jnp.argmin tie-break).
// ---------------------------------------------------------------------------
__global__ __launch_bounds__(128) void argmin_onehot_kernel(
    const float* __restrict__ cb, float* __restrict__ out)
{
    __shared__ float cbs[128 * 64];
    __shared__ float cns[128];

    const int tid = threadIdx.x;
    const int n   = blockIdx.x * 128 + tid;

    float zr[64];
#pragma unroll
    for (int c = 0; c < 64; c++)
        zr[c] = g_z3[c * 21632 + n];

    float best = 3.4e38f;
    int   bidx = 0;

    for (int t = 0; t < 4; t++) {
        __syncthreads();
        // stage 128 codes (32 KB) into smem
        const float4* src = reinterpret_cast<const float4*>(cb + t * 128 * 64);
        float4* dst = reinterpret_cast<float4*>(cbs);
#pragma unroll
        for (int i = 0; i < 16; i++)
            dst[tid + i * 128] = src[tid + i * 128];
        cns[tid] = g_cnorm[t * 128 + tid];
        __syncthreads();

        for (int j = 0; j < 128; j++) {
            const float* cr = cbs + j * 64;  // broadcast reads across the warp
            float d0 = 0.f, d1 = 0.f, d2 = 0.f, d3 = 0.f;
#pragma unroll
            for (int c = 0; c < 64; c += 4) {
                d0 += zr[c + 0] * cr[c + 0];
                d1 += zr[c + 1] * cr[c + 1];
                d2 += zr[c + 2] * cr[c + 2];
                d3 += zr[c + 3] * cr[c + 3];
            }
            const float score = cns[j] - 2.f * ((d0 + d1) + (d2 + d3));
            const int gidx = t * 128 + j;
            if (score < best) { best = score; bidx = gidx; }
        }
    }

    const int b = n / 169;
    const int p = n % 169;
    out[((size_t)b * 512 + bidx) * 169 + p] = 1.0f;
}

// ---------------------------------------------------------------------------
extern "C" void kernel_launch(void* const* d_in, const int* in_sizes, int n_in,
                              void* d_out, int out_size)
{
    const float* x  = (const float*)d_in[0];
    const float* w1 = (const float*)d_in[1];
    const float* b1 = (const float*)d_in[2];
    const float* w2 = (const float*)d_in[3];
    const float* b2 = (const float*)d_in[4];
    const float* w3 = (const float*)d_in[5];
    const float* b3 = (const float*)d_in[6];
    const float* cb = (const float*)d_in[7];
    float* out = (float*)d_out;

    float *z1, *z2, *z3;
    cudaGetSymbolAddress((void**)&z1, g_z1);
    cudaGetSymbolAddress((void**)&z2, g_z2);
    cudaGetSymbolAddress((void**)&z3, g_z3);

    // output is a one-hot: zero it, scatter the ones later
    cudaMemsetAsync(out, 0, (size_t)out_size * sizeof(float));

    // conv1: 3->64, 8x8 s4 p2, 192->48, ReLU, NCHW out.  N = 128*2304 = 294912
    conv_gemm_kernel<3, 8, 8, 192, 192, 48, 48, 4, 2, 64, true, 0>
        <<<dim3(294912 / 64, 1), 256>>>(x, w1, b1, z1);

    // conv2: 64->128, 6x6 s3 p2, 48->16, ReLU, NCHW out.  N = 128*256 = 32768
    conv_gemm_kernel<64, 6, 6, 48, 48, 16, 16, 3, 2, 128, true, 0>
        <<<dim3(32768 / 64, 2), 256>>>(z1, w2, b2, z2);

    // conv3: 128->64, 4x4 s1 p0, 16->13, no ReLU, [C][N] out.  N = 128*169 = 21632
    conv_gemm_kernel<128, 4, 4, 16, 16, 13, 13, 1, 0, 64, false, 1>
        <<<dim3(21632 / 64, 1), 256>>>(z2, w3, b3, z3);

    cnorm_kernel<<<2, 256>>>(cb);

    argmin_onehot_kernel<<<21632 / 128, 128>>>(cb, out);
}